// round 11
// baseline (speedup 1.0000x reference)
#include <cuda_runtime.h>
#include <stdint.h>

#define BB 4
#define NN 4096
#define DD 128
#define KK 2048
#define EPSV 1e-10f
#define NBLK 888          // persistent gatherg blocks (148 SMs x 6)
#define TOTROWS (BB * KK) // 8192 flattened output rows

// ---- scratch (no allocation allowed) ----
__device__ unsigned long long d_keys[BB * NN];   // 128 KB
__device__ int   d_idx[BB * KK];
__device__ float d_vals[BB * KK];

// output layout: g_new | new_h | idx (float32)
#define OFF_G 0
#define OFF_H ((size_t)BB * KK * KK)
#define OFF_I (OFF_H + (size_t)BB * KK * DD)

__device__ __forceinline__ unsigned smem_u32(const void* p) {
    unsigned a;
    asm("{ .reg .u64 t; cvta.to.shared.u64 t, %1; cvt.u32.u64 %0, t; }" : "=r"(a) : "l"(p));
    return a;
}

// ---------------------------------------------------------------------------
// Kernel 1: scores = sigmoid(h . w + b) packed into sortable u64 keys.
// key = (score_bits << 32) | (0xFFFFFFFF - node): descending key order ==
// descending score, ascending node on ties (jax.lax.top_k). 4 nodes/warp.
// ---------------------------------------------------------------------------
__global__ void scores_kernel(const float4* __restrict__ h,
                              const float4* __restrict__ w,
                              const float* __restrict__ bptr) {
    int gwarp = (blockIdx.x * blockDim.x + threadIdx.x) >> 5;
    int lane  = threadIdx.x & 31;
    int n0 = gwarp * 4;
    if (n0 >= BB * NN) return;
    float4 wv = w[lane];
    float s[4];
    #pragma unroll
    for (int u = 0; u < 4; u++) {
        float4 a = h[(size_t)(n0 + u) * (DD / 4) + lane];
        s[u] = a.x * wv.x + a.y * wv.y + a.z * wv.z + a.w * wv.w;
    }
    #pragma unroll
    for (int o = 16; o; o >>= 1) {
        #pragma unroll
        for (int u = 0; u < 4; u++) s[u] += __shfl_xor_sync(0xFFFFFFFFu, s[u], o);
    }
    if (lane < 4) {
        int nd = n0 + lane;
        float x  = s[lane] + bptr[0];
        float sc = 1.0f / (1.0f + expf(-x));
        unsigned int sb = __float_as_uint(sc);
        unsigned int node = (unsigned int)(nd & (NN - 1));
        d_keys[nd] = ((unsigned long long)sb << 32) |
                     (unsigned long long)(0xFFFFFFFFu - node);
    }
}

// ---------------------------------------------------------------------------
// Kernel 2: exact rank-by-count (keys unique). 512 threads / 128 nodes per
// block: each node's 4096 compares split across FOUR threads.
// ---------------------------------------------------------------------------
__global__ void __launch_bounds__(512) rank_kernel() {
    __shared__ __align__(16) unsigned long long sk[NN];   // 32 KB
    __shared__ int part[3][128];
    const int b   = blockIdx.x >> 5;
    const int blk = blockIdx.x & 31;
    const int tid = threadIdx.x;
    for (int i = tid; i < NN; i += 512) sk[i] = d_keys[b * NN + i];
    __syncthreads();

    const int node = blk * 128 + (tid & 127);
    const int q    = tid >> 7;
    const unsigned long long my = sk[node];
    const ulonglong2* sk2 = (const ulonglong2*)(sk + q * (NN / 4));
    int r = 0;
    #pragma unroll 8
    for (int i = 0; i < NN / 8; i++) {
        ulonglong2 kk = sk2[i];
        r += (kk.x > my) + (kk.y > my);
    }
    if (q) part[q - 1][tid & 127] = r;
    __syncthreads();
    if (!q) {
        r += part[0][tid] + part[1][tid] + part[2][tid];
        if (r < KK) {
            d_idx [b * KK + r] = node;
            d_vals[b * KK + r] = __uint_as_float((unsigned int)(my >> 32));
        }
    }
}

// ---------------------------------------------------------------------------
// Kernel 3: PERSISTENT gathered adjacency + degree normalize + new_h + idx.
// One wave of 888 blocks; each walks a contiguous chunk of the 8192 output
// rows with a 2-stage cp.async pipeline running across the whole chunk:
// fill latency paid once per block, no wave-quantization tail.
// ---------------------------------------------------------------------------
__global__ void __launch_bounds__(256) gatherg_kernel(const float* __restrict__ g,
                                                      const float* __restrict__ h,
                                                      float* __restrict__ out) {
    __shared__ __align__(16) float buf[2][NN];              // 32 KB
    __shared__ float wsum[8];

    const int tid = threadIdx.x;
    // contiguous chunk [r0, r1) of flattened rows
    const int per  = TOTROWS / NBLK;                        // 9
    const int rem  = TOTROWS % NBLK;                        // 200
    const int r0   = blockIdx.x * per + min(blockIdx.x, rem);
    const int r1   = r0 + per + (blockIdx.x < rem ? 1 : 0);

    auto issue_row = [&](int rr, int st) {                  // rr = flattened row
        const int bb   = rr >> 11;
        const int node = d_idx[rr];
        const char* gsrc = (const char*)(g + ((size_t)bb * NN + node) * NN) + tid * 16;
        unsigned sdst = smem_u32(buf[st]) + tid * 16;
        #pragma unroll
        for (int c = 0; c < 4; c++) {
            asm volatile("cp.async.cg.shared.global [%0], [%1], 16;"
                         :: "r"(sdst + c * 4096), "l"(gsrc + c * 4096) : "memory");
        }
        asm volatile("cp.async.commit_group;" ::: "memory");
    };

    issue_row(r0, 0);
    if (r0 + 1 < r1) issue_row(r0 + 1, 1);

    for (int rr = r0; rr < r1; rr++) {
        const int   st   = (rr - r0) & 1;
        const int   b    = rr >> 11;
        const int   node = d_idx[rr];
        const float v    = d_vals[rr];

        // per-row column indices (L1/L2-hot: 8 KB per batch)
        const int4* cp4 = (const int4*)(d_idx + b * KK);
        const int4 c0 = cp4[tid * 2];
        const int4 c1 = cp4[tid * 2 + 1];

        // fused new_h + idx (independent of buf; overlaps pending copies)
        if (tid < 32) {
            float4 hv = __ldg((const float4*)(h + ((size_t)b * NN + node) * DD) + tid);
            hv.x *= v; hv.y *= v; hv.z *= v; hv.w *= v;
            ((float4*)(out + OFF_H + (size_t)rr * DD))[tid] = hv;
        }
        if (tid == 32) out[OFF_I + rr] = (float)node;

        if (rr < r1 - 1)
            asm volatile("cp.async.wait_group 1;" ::: "memory");
        else
            asm volatile("cp.async.wait_group 0;" ::: "memory");
        __syncthreads();

        const float* srow = buf[st];
        float vv[8];
        vv[0] = srow[c0.x]; vv[1] = srow[c0.y]; vv[2] = srow[c0.z]; vv[3] = srow[c0.w];
        vv[4] = srow[c1.x]; vv[5] = srow[c1.y]; vv[6] = srow[c1.z]; vv[7] = srow[c1.w];
        float local = (vv[0] + vv[1]) + (vv[2] + vv[3]) +
                      ((vv[4] + vv[5]) + (vv[6] + vv[7]));
        #pragma unroll
        for (int o = 16; o; o >>= 1) local += __shfl_xor_sync(0xFFFFFFFFu, local, o);
        if ((tid & 31) == 0) wsum[tid >> 5] = local;
        __syncthreads();

        float deg = 0.f;
        #pragma unroll
        for (int wv = 0; wv < 8; wv++) deg += wsum[wv];
        const float inv = 1.0f / (deg + EPSV);

        if (rr + 2 < r1) issue_row(rr + 2, st);  // refill before the writes

        float4* dst4 = (float4*)(out + OFF_G + (size_t)rr * KK);
        dst4[tid * 2]     = make_float4(vv[0] * inv, vv[1] * inv, vv[2] * inv, vv[3] * inv);
        dst4[tid * 2 + 1] = make_float4(vv[4] * inv, vv[5] * inv, vv[6] * inv, vv[7] * inv);
    }
}

// ---------------------------------------------------------------------------
extern "C" void kernel_launch(void* const* d_in, const int* in_sizes, int n_in,
                              void* d_out, int out_size) {
    const float* g = (const float*)d_in[0];   // [B,N,N]
    const float* h = (const float*)d_in[1];   // [B,N,D]
    const float* w = (const float*)d_in[2];   // [D]
    const float* b = (const float*)d_in[3];   // scalar
    float* out = (float*)d_out;

    scores_kernel<<<(BB * NN) / 16, 128>>>((const float4*)h, (const float4*)w, b);
    rank_kernel<<<BB * 32, 512>>>();
    gatherg_kernel<<<NBLK, 256>>>(g, h, out);
}

// round 13
// speedup vs baseline: 1.0602x; 1.0602x over previous
#include <cuda_runtime.h>
#include <stdint.h>

#define BB 4
#define NN 4096
#define DD 128
#define KK 2048
#define EPSV 1e-10f
#define RPB 4     // rows per gatherg block

// ---- scratch (no allocation allowed) ----
__device__ unsigned long long d_keys[BB * NN];   // 128 KB
__device__ int   d_idx[BB * KK];
__device__ float d_vals[BB * KK];

// output layout: g_new | new_h | idx (float32)
#define OFF_G 0
#define OFF_H ((size_t)BB * KK * KK)
#define OFF_I (OFF_H + (size_t)BB * KK * DD)

__device__ __forceinline__ unsigned smem_u32(const void* p) {
    unsigned a;
    asm("{ .reg .u64 t; cvta.to.shared.u64 t, %1; cvt.u32.u64 %0, t; }" : "=r"(a) : "l"(p));
    return a;
}

// ---------------------------------------------------------------------------
// Kernel 1: scores = sigmoid(h . w + b) packed into sortable u64 keys.
// key = (score_bits << 32) | (0xFFFFFFFF - node): descending key order ==
// descending score, ascending node on ties (jax.lax.top_k). 4 nodes/warp,
// 512-thread blocks.
// ---------------------------------------------------------------------------
__global__ void __launch_bounds__(512) scores_kernel(const float4* __restrict__ h,
                                                     const float4* __restrict__ w,
                                                     const float* __restrict__ bptr) {
    int gwarp = (blockIdx.x * blockDim.x + threadIdx.x) >> 5;
    int lane  = threadIdx.x & 31;
    int n0 = gwarp * 4;
    if (n0 >= BB * NN) return;
    float4 wv = w[lane];
    float s[4];
    #pragma unroll
    for (int u = 0; u < 4; u++) {
        float4 a = h[(size_t)(n0 + u) * (DD / 4) + lane];
        s[u] = a.x * wv.x + a.y * wv.y + a.z * wv.z + a.w * wv.w;
    }
    #pragma unroll
    for (int o = 16; o; o >>= 1) {
        #pragma unroll
        for (int u = 0; u < 4; u++) s[u] += __shfl_xor_sync(0xFFFFFFFFu, s[u], o);
    }
    if (lane < 4) {
        int nd = n0 + lane;
        float x  = s[lane] + bptr[0];
        float sc = 1.0f / (1.0f + expf(-x));
        unsigned int sb = __float_as_uint(sc);
        unsigned int node = (unsigned int)(nd & (NN - 1));
        d_keys[nd] = ((unsigned long long)sb << 32) |
                     (unsigned long long)(0xFFFFFFFFu - node);
    }
}

// ---------------------------------------------------------------------------
// Kernel 2: exact rank-by-count (keys unique). 1024 threads / 128 nodes per
// block: each node's 4096 compares split across EIGHT threads (512 keys
// each), partials combined in smem. 32 blocks/batch = 128 blocks, one wave.
// ---------------------------------------------------------------------------
__global__ void __launch_bounds__(1024) rank_kernel() {
    __shared__ __align__(16) unsigned long long sk[NN];   // 32 KB
    __shared__ int part[7][128];                          // 3.5 KB
    const int b   = blockIdx.x >> 5;
    const int blk = blockIdx.x & 31;
    const int tid = threadIdx.x;           // 1024 threads
    for (int i = tid; i < NN; i += 1024) sk[i] = d_keys[b * NN + i];
    __syncthreads();

    const int node = blk * 128 + (tid & 127);
    const int e    = tid >> 7;             // eighth 0..7
    const unsigned long long my = sk[node];
    const ulonglong2* sk2 = (const ulonglong2*)(sk + e * (NN / 8));
    int r = 0;
    #pragma unroll 8
    for (int i = 0; i < NN / 16; i++) {    // 256 iters x 2 keys
        ulonglong2 kk = sk2[i];
        r += (kk.x > my) + (kk.y > my);
    }
    if (e) part[e - 1][tid & 127] = r;
    __syncthreads();
    if (!e) {
        #pragma unroll
        for (int p = 0; p < 7; p++) r += part[p][tid];
        if (r < KK) {
            d_idx [b * KK + r] = node;
            d_vals[b * KK + r] = __uint_as_float((unsigned int)(my >> 32));
        }
    }
}

// ---------------------------------------------------------------------------
// Kernel 3: gathered adjacency + degree normalize, fused new_h + idx.
// Exact R10 version (measured best): 2-stage cp.async, lookahead 1, RPB=4,
// 512 threads, one STG.128 per thread per row.
// ---------------------------------------------------------------------------
__global__ void __launch_bounds__(512) gatherg_kernel(const float* __restrict__ g,
                                                      const float* __restrict__ h,
                                                      float* __restrict__ out) {
    __shared__ __align__(16) float buf[2][NN];              // 32 KB
    __shared__ float wsum[16];

    const int b    = blockIdx.y;
    const int base = blockIdx.x * RPB;
    const int tid  = threadIdx.x;

    auto issue_row = [&](int r, int st) {
        const int node = d_idx[b * KK + base + r];
        const char* gsrc = (const char*)(g + ((size_t)b * NN + node) * NN) + tid * 16;
        unsigned sdst = smem_u32(buf[st]) + tid * 16;
        #pragma unroll
        for (int c = 0; c < 2; c++) {
            asm volatile("cp.async.cg.shared.global [%0], [%1], 16;"
                         :: "r"(sdst + c * 8192), "l"(gsrc + c * 8192) : "memory");
        }
        asm volatile("cp.async.commit_group;" ::: "memory");
    };

    issue_row(0, 0);
    issue_row(1, 1);

    const int4 c0 = ((const int4*)(d_idx + b * KK))[tid];

    #pragma unroll
    for (int r = 0; r < RPB; r++) {
        const int   st   = r & 1;
        const int   row  = b * KK + base + r;
        const int   node = d_idx[row];
        const float v    = d_vals[row];

        if (tid < 32) {
            float4 hv = __ldg((const float4*)(h + ((size_t)b * NN + node) * DD) + tid);
            hv.x *= v; hv.y *= v; hv.z *= v; hv.w *= v;
            ((float4*)(out + OFF_H + (size_t)row * DD))[tid] = hv;
        }
        if (tid == 32) out[OFF_I + row] = (float)node;

        if (r < RPB - 1)
            asm volatile("cp.async.wait_group 1;" ::: "memory");
        else
            asm volatile("cp.async.wait_group 0;" ::: "memory");
        __syncthreads();

        const float* srow = buf[st];
        float vv[4];
        vv[0] = srow[c0.x]; vv[1] = srow[c0.y]; vv[2] = srow[c0.z]; vv[3] = srow[c0.w];
        float local = (vv[0] + vv[1]) + (vv[2] + vv[3]);
        #pragma unroll
        for (int o = 16; o; o >>= 1) local += __shfl_xor_sync(0xFFFFFFFFu, local, o);
        if ((tid & 31) == 0) wsum[tid >> 5] = local;
        __syncthreads();

        float deg = 0.f;
        #pragma unroll
        for (int wv = 0; wv < 16; wv++) deg += wsum[wv];
        const float inv = 1.0f / (deg + EPSV);

        if (r + 2 < RPB) issue_row(r + 2, st);

        float4* dst4 = (float4*)(out + OFF_G + (size_t)row * KK);
        dst4[tid] = make_float4(vv[0] * inv, vv[1] * inv, vv[2] * inv, vv[3] * inv);
    }
}

// ---------------------------------------------------------------------------
extern "C" void kernel_launch(void* const* d_in, const int* in_sizes, int n_in,
                              void* d_out, int out_size) {
    const float* g = (const float*)d_in[0];   // [B,N,N]
    const float* h = (const float*)d_in[1];   // [B,N,D]
    const float* w = (const float*)d_in[2];   // [D]
    const float* b = (const float*)d_in[3];   // scalar
    float* out = (float*)d_out;

    scores_kernel<<<(BB * NN) / 64, 512>>>((const float4*)h, (const float4*)w, b);
    rank_kernel<<<BB * 32, 1024>>>();
    dim3 grid(KK / RPB, BB);
    gatherg_kernel<<<grid, 512>>>(g, h, out);
}